// round 1
// baseline (speedup 1.0000x reference)
#include <cuda_runtime.h>

// LocalVariation: out[b, k, y, x] = x[b,0,y,x] - x_pad[b,0,y+i,x+j]
// for the 24 off-center (i,j) in a 5x5 window, replicate padding.
// Shapes: x [16,1,512,512] f32 -> out [16,24,512,512] f32.
//
// Store-bandwidth bound: ~402 MB out + ~17 MB in. Strategy: shared halo tile,
// float4 vectorized compute + stores, fully coalesced per-channel writes.

#define HH 512
#define WW 512
#define NB 16
#define NC 24
#define TX 128   // tile width in pixels (32 threads x float4)
#define TY 8     // tile height
#define SW 132   // TX + 4 halo
#define SH 12    // TY + 4 halo

__global__ __launch_bounds__(256, 4)
void local_variation_kernel(const float* __restrict__ x, float* __restrict__ out) {
    __shared__ float s[SH][SW];

    const int tid = threadIdx.y * 32 + threadIdx.x;
    const int x0 = blockIdx.x * TX;
    const int y0 = blockIdx.y * TY;
    const int b  = blockIdx.z;

    const float* __restrict__ xb = x + (size_t)b * HH * WW;

    // Cooperative halo load with replicate-pad clamping.
    // SH*SW = 1584 elements, 256 threads -> ~6.2 loads/thread.
    #pragma unroll
    for (int idx = tid; idx < SH * SW; idx += 256) {
        int r = idx / SW;
        int c = idx - r * SW;
        int gy = y0 + r - 2;
        int gx = x0 + c - 2;
        gy = min(max(gy, 0), HH - 1);
        gx = min(max(gx, 0), WW - 1);
        s[r][c] = __ldg(&xb[gy * WW + gx]);
    }
    __syncthreads();

    const int sx = threadIdx.x * 4;   // tile-local column of first pixel
    const int sy = threadIdx.y;       // tile-local row

    // Load the 5x8 neighborhood this thread needs (two float4 per row,
    // 16B-aligned: row stride 132 floats ≡ 0 mod 4, sx ≡ 0 mod 4).
    float r[5][8];
    #pragma unroll
    for (int i = 0; i < 5; i++) {
        float4 lo = *reinterpret_cast<const float4*>(&s[sy + i][sx]);
        float4 hi = *reinterpret_cast<const float4*>(&s[sy + i][sx + 4]);
        r[i][0] = lo.x; r[i][1] = lo.y; r[i][2] = lo.z; r[i][3] = lo.w;
        r[i][4] = hi.x; r[i][5] = hi.y; r[i][6] = hi.z; r[i][7] = hi.w;
    }

    const float c0 = r[2][2], c1 = r[2][3], c2 = r[2][4], c3 = r[2][5];

    const int gy = y0 + sy;
    const int gx = x0 + sx;
    float* __restrict__ ob = out + (((size_t)b * NC) * HH + gy) * WW + gx;
    const size_t plane = (size_t)HH * WW;

    int k = 0;
    #pragma unroll
    for (int i = 0; i < 5; i++) {
        #pragma unroll
        for (int j = 0; j < 5; j++) {
            if (i == 2 && j == 2) continue;
            float4 o;
            o.x = c0 - r[i][j + 0];
            o.y = c1 - r[i][j + 1];
            o.z = c2 - r[i][j + 2];
            o.w = c3 - r[i][j + 3];
            *reinterpret_cast<float4*>(ob + (size_t)k * plane) = o;
            k++;
        }
    }
}

extern "C" void kernel_launch(void* const* d_in, const int* in_sizes, int n_in,
                              void* d_out, int out_size) {
    const float* x = (const float*)d_in[0];
    float* out = (float*)d_out;
    dim3 block(32, 8, 1);
    dim3 grid(WW / TX, HH / TY, NB);   // 4 x 64 x 16 = 4096 blocks
    local_variation_kernel<<<grid, block>>>(x, out);
}

// round 2
// speedup vs baseline: 1.4139x; 1.4139x over previous
#include <cuda_runtime.h>

// LocalVariation: out[b, k, y, x] = x[b,0,y,x] - x_pad[b,0,y+i,x+j]
// 24 off-center (i,j) in 5x5 window, replicate padding.
// x [16,1,512,512] f32 -> out [16,24,512,512] f32.
//
// R2: register-rolling row window. Each thread: 4 px wide x 4 rows tall.
// Tile 128x32 per 256-thread block; smem 36x132 halo tile. Per output row
// only 1 new smem row is loaded (2 LDS.128), cutting input-side L1 traffic
// ~2.5x vs R1. Streaming stores (__stcs) since output is write-once.

#define HH 512
#define WW 512
#define NB 16
#define NC 24
#define TX 128   // tile width (32 threads x float4)
#define TYO 32   // tile height (8 threads x 4 rows)
#define SW 132   // TX + 4 halo
#define SH 36    // TYO + 4 halo

__global__ __launch_bounds__(256)
void local_variation_kernel(const float* __restrict__ x, float* __restrict__ out) {
    __shared__ float s[SH][SW];

    const int tid = threadIdx.y * 32 + threadIdx.x;
    const int x0 = blockIdx.x * TX;
    const int y0 = blockIdx.y * TYO;
    const int b  = blockIdx.z;

    const float* __restrict__ xb = x + (size_t)b * HH * WW;

    // Cooperative halo load with replicate-pad clamping. SH*SW = 4752 elems.
    for (int idx = tid; idx < SH * SW; idx += 256) {
        int r = idx / SW;
        int c = idx - r * SW;
        int gy = min(max(y0 + r - 2, 0), HH - 1);
        int gx = min(max(x0 + c - 2, 0), WW - 1);
        s[r][c] = __ldg(&xb[gy * WW + gx]);
    }
    __syncthreads();

    const int sx = threadIdx.x * 4;       // tile-local col of first pixel
    const int rb = threadIdx.y * 4;       // first output row (tile-local)

    // 5-row x 8-float rolling register window.
    // Window invariant at step t: slot (t+i)%5 holds smem row rb+t+i.
    float w[5][8];
    #pragma unroll
    for (int i = 0; i < 5; i++) {
        float4 lo = *reinterpret_cast<const float4*>(&s[rb + i][sx]);
        float4 hi = *reinterpret_cast<const float4*>(&s[rb + i][sx + 4]);
        w[i][0] = lo.x; w[i][1] = lo.y; w[i][2] = lo.z; w[i][3] = lo.w;
        w[i][4] = hi.x; w[i][5] = hi.y; w[i][6] = hi.z; w[i][7] = hi.w;
    }

    const int gy0 = y0 + rb;
    const int gx  = x0 + sx;
    float* __restrict__ ob = out + (((size_t)b * NC) * HH + gy0) * WW + gx;
    const size_t plane = (size_t)HH * WW;

    #pragma unroll
    for (int t = 0; t < 4; t++) {
        const float* cw = w[(t + 2) % 5];
        const float c0 = cw[2], c1 = cw[3], c2 = cw[4], c3 = cw[5];

        float* __restrict__ orow = ob + t * WW;
        int k = 0;
        #pragma unroll
        for (int i = 0; i < 5; i++) {
            const float* rr = w[(t + i) % 5];
            #pragma unroll
            for (int j = 0; j < 5; j++) {
                if (i == 2 && j == 2) continue;
                float4 o;
                o.x = c0 - rr[j + 0];
                o.y = c1 - rr[j + 1];
                o.z = c2 - rr[j + 2];
                o.w = c3 - rr[j + 3];
                __stcs(reinterpret_cast<float4*>(orow + (size_t)k * plane), o);
                k++;
            }
        }

        // Roll: slot t%5 (held row rb+t) <- smem row rb+t+5.
        if (t < 3) {
            float4 lo = *reinterpret_cast<const float4*>(&s[rb + t + 5][sx]);
            float4 hi = *reinterpret_cast<const float4*>(&s[rb + t + 5][sx + 4]);
            float* d = w[t % 5];
            d[0] = lo.x; d[1] = lo.y; d[2] = lo.z; d[3] = lo.w;
            d[4] = hi.x; d[5] = hi.y; d[6] = hi.z; d[7] = hi.w;
        }
    }
}

extern "C" void kernel_launch(void* const* d_in, const int* in_sizes, int n_in,
                              void* d_out, int out_size) {
    const float* x = (const float*)d_in[0];
    float* out = (float*)d_out;
    dim3 block(32, 8, 1);
    dim3 grid(WW / TX, HH / TYO, NB);   // 4 x 16 x 16 = 1024 blocks
    local_variation_kernel<<<grid, block>>>(x, out);
}

// round 3
// speedup vs baseline: 1.5448x; 1.0925x over previous
#include <cuda_runtime.h>

// LocalVariation: out[b, k, y, x] = x[b,0,y,x] - x_pad[b,0,y+i,x+j]
// 24 off-center (i,j) in 5x5 window, replicate padding.
// x [16,1,512,512] f32 -> out [16,24,512,512] f32.
//
// R3: fix wave quantization. R2 had 1024 blocks vs 740 concurrent -> 2 waves,
// second wave 38% full (~30% idle machine time). Tile 128x16 per 256-thread
// block -> 2048 blocks, ~2.8 waves, tail waste <8%. Keeps the register-rolling
// row window (2 rows/thread) + float4 streaming stores.

#define HH 512
#define WW 512
#define NB 16
#define NC 24
#define TX 128   // tile width (32 threads x float4)
#define TYO 16   // tile height (8 threads x 2 rows)
#define SW 132   // TX + 4 halo
#define SH 20    // TYO + 4 halo

__global__ __launch_bounds__(256)
void local_variation_kernel(const float* __restrict__ x, float* __restrict__ out) {
    __shared__ float s[SH][SW];

    const int tid = threadIdx.y * 32 + threadIdx.x;
    const int x0 = blockIdx.x * TX;
    const int y0 = blockIdx.y * TYO;
    const int b  = blockIdx.z;

    const float* __restrict__ xb = x + (size_t)b * HH * WW;

    // Cooperative halo load with replicate-pad clamping. SH*SW = 2640 elems.
    for (int idx = tid; idx < SH * SW; idx += 256) {
        int r = idx / SW;
        int c = idx - r * SW;
        int gy = min(max(y0 + r - 2, 0), HH - 1);
        int gx = min(max(x0 + c - 2, 0), WW - 1);
        s[r][c] = __ldg(&xb[gy * WW + gx]);
    }
    __syncthreads();

    const int sx = threadIdx.x * 4;       // tile-local col of first pixel
    const int rb = threadIdx.y * 2;       // first output row (tile-local)

    // 5-row x 8-float rolling register window.
    // Invariant at step t: slot (t+i)%5 holds smem row rb+t+i.
    float w[5][8];
    #pragma unroll
    for (int i = 0; i < 5; i++) {
        float4 lo = *reinterpret_cast<const float4*>(&s[rb + i][sx]);
        float4 hi = *reinterpret_cast<const float4*>(&s[rb + i][sx + 4]);
        w[i][0] = lo.x; w[i][1] = lo.y; w[i][2] = lo.z; w[i][3] = lo.w;
        w[i][4] = hi.x; w[i][5] = hi.y; w[i][6] = hi.z; w[i][7] = hi.w;
    }

    const int gy0 = y0 + rb;
    const int gx  = x0 + sx;
    float* __restrict__ ob = out + (((size_t)b * NC) * HH + gy0) * WW + gx;
    const size_t plane = (size_t)HH * WW;

    #pragma unroll
    for (int t = 0; t < 2; t++) {
        const float* cw = w[(t + 2) % 5];
        const float c0 = cw[2], c1 = cw[3], c2 = cw[4], c3 = cw[5];

        float* __restrict__ orow = ob + t * WW;
        int k = 0;
        #pragma unroll
        for (int i = 0; i < 5; i++) {
            const float* rr = w[(t + i) % 5];
            #pragma unroll
            for (int j = 0; j < 5; j++) {
                if (i == 2 && j == 2) continue;
                float4 o;
                o.x = c0 - rr[j + 0];
                o.y = c1 - rr[j + 1];
                o.z = c2 - rr[j + 2];
                o.w = c3 - rr[j + 3];
                __stcs(reinterpret_cast<float4*>(orow + (size_t)k * plane), o);
                k++;
            }
        }

        // Roll: slot t%5 (held row rb+t) <- smem row rb+t+5.
        if (t < 1) {
            float4 lo = *reinterpret_cast<const float4*>(&s[rb + t + 5][sx]);
            float4 hi = *reinterpret_cast<const float4*>(&s[rb + t + 5][sx + 4]);
            float* d = w[t % 5];
            d[0] = lo.x; d[1] = lo.y; d[2] = lo.z; d[3] = lo.w;
            d[4] = hi.x; d[5] = hi.y; d[6] = hi.z; d[7] = hi.w;
        }
    }
}

extern "C" void kernel_launch(void* const* d_in, const int* in_sizes, int n_in,
                              void* d_out, int out_size) {
    const float* x = (const float*)d_in[0];
    float* out = (float*)d_out;
    dim3 block(32, 8, 1);
    dim3 grid(WW / TX, HH / TYO, NB);   // 4 x 32 x 16 = 2048 blocks
    local_variation_kernel<<<grid, block>>>(x, out);
}